// round 16
// baseline (speedup 1.0000x reference)
#include <cuda_runtime.h>
#include <cstdint>

// Problem constants (fixed by the dataset)
#define BQ    128
#define TT    512
#define CC    1024
#define LL    64
#define SS    129           // 2*LL + 1 extended states
#define BLANKC 1023
#define EPSF  1e-7f
#define JPER  5             // states per lane (26 lanes * 5 = 130 >= 129)
#define DEPTH 16            // cp.async pipeline depth (steps in flight)
#define RSTRIDE 68          // smem ring row stride (66 used, padded)
#define EF_TARGET 226       // rescale target: warp max in [2^99, 2^100)

__device__ __forceinline__ void cpasync4(uint32_t saddr, const float* g) {
    asm volatile("cp.async.ca.shared.global [%0], [%1], 4;" :: "r"(saddr), "l"(g));
}
__device__ __forceinline__ void cpcommit() {
    asm volatile("cp.async.commit_group;");
}
template <int N> __device__ __forceinline__ void cpwait() {
    asm volatile("cp.async.wait_group %0;" :: "n"(N));
}

__device__ __forceinline__ float pick5(const float a0, const float a1, const float a2,
                                       const float a3, const float a4, int j) {
    float r = a0;
    if (j == 1) r = a1;
    else if (j == 2) r = a2;
    else if (j == 3) r = a3;
    else if (j == 4) r = a4;
    return r;
}

__global__ __launch_bounds__(32, 1)
void ctc_fused_kernel(const int* __restrict__ y_true,
                      const float* __restrict__ y_pred,
                      const int* __restrict__ input_length,
                      const int* __restrict__ label_length,
                      float* __restrict__ out)
{
    __shared__ float ring[DEPTH][RSTRIDE];   // per-step compact emissions (66 used)

    const int b    = blockIdx.x;
    const int lane = threadIdx.x;
    const unsigned FULL = 0xffffffffu;

    const int Tb = input_length[b];          // warp-uniform
    const int Ll = label_length[b];
    const int Sb = 2 * Ll + 1;

    const int*   lrow = y_true + b * LL;
    const float* prow = y_pred + (size_t)b * TT * CC;

    // Each lane gathers label classes lane and lane+32; lane 0 also the blank.
    const int lab0 = lrow[lane];
    const int lab1 = lrow[lane + 32];

    const uint32_t smem_base = (uint32_t)__cvta_generic_to_shared(&ring[0][0]);

    // Per-lane static state metadata: states s = lane*5 + j
    int   off[JPER];     // index into compact emission row (s>>1 label, 64 blank)
    float vsf[JPER];     // validity mask (0 for invalid states)
    float skipf[JPER];
#pragma unroll
    for (int j = 0; j < JPER; j++) {
        const int s = lane * JPER + j;
        const bool v = (s < SS) && (s < Sb);
        int  o  = 64;                       // blank slot (also sink for invalid)
        bool sk = false;
        if (v && (s & 1)) {
            o = s >> 1;
            if (s >= 3) sk = (lrow[o] != lrow[o - 1]);
        }
        off[j]   = o;
        vsf[j]   = v ? 1.0f : 0.0f;
        skipf[j] = sk ? 1.0f : 0.0f;
    }

    // alpha init: linear domain, mass 1 at s=0
    float a0 = 0.f, a1r = 0.f, a2r = 0.f, a3r = 0.f, a4r = 0.f;
    if (lane == 0) a0 = 1.0f;

    // ---- prologue: fill the cp.async pipeline with steps 0..DEPTH-1 ----
#pragma unroll
    for (int t = 0; t < DEPTH; t++) {
        const float* pr = prow + (size_t)t * CC;
        const uint32_t wa = smem_base + (uint32_t)((t & (DEPTH - 1)) * RSTRIDE + lane) * 4u;
        cpasync4(wa, pr + lab0);
        cpasync4(wa + 32u * 4u, pr + lab1);
        if (lane == 0)
            cpasync4(smem_base + (uint32_t)((t & (DEPTH - 1)) * RSTRIDE + 64) * 4u, pr + BLANKC);
        cpcommit();
    }

    // ee[parity][j]: emission values for the current / next step, EPS and
    // validity (and any pending rescale factor) pre-folded.
    float ee[2][JPER];
    cpwait<DEPTH - 1>();                     // step 0 group complete
#pragma unroll
    for (int j = 0; j < JPER; j++)
        ee[0][j] = (ring[0][off[j]] + EPSF) * vsf[j];

    int esum = 0;   // exact power-of-two rescale accumulator
                    // invariant: alpha_true = alpha_stored * 2^esum

    for (int tb = 0; tb < Tb; tb += 4) {
#pragma unroll
        for (int k = 0; k < 4; k++) {
            const int t   = tb + k;
            const int cur = t & 1;
            const int nxt = cur ^ 1;

            // 1) issue prefetch for step t+DEPTH — ONLY if that row is actually
            //    consumed (tp < Tb). Commit unconditionally so the group counter
            //    keeps the wait<15> residency guarantee identical to before.
            {
                const int tp = t + DEPTH;
                if (tp < Tb) {
                    const float* pr = prow + (size_t)tp * CC;
                    const uint32_t wa = smem_base + (uint32_t)((tp & (DEPTH - 1)) * RSTRIDE + lane) * 4u;
                    cpasync4(wa, pr + lab0);
                    cpasync4(wa + 32u * 4u, pr + lab1);
                    if (lane == 0)
                        cpasync4(smem_base + (uint32_t)((tp & (DEPTH - 1)) * RSTRIDE + 64) * 4u, pr + BLANKC);
                }
                cpcommit();
            }
            // 2) ensure step t+1's group is complete, read its raw values.
            //    (rows >= Tb read stale slots; they only feed steps guarded off)
            cpwait<DEPTH - 1>();
            float r[JPER];
            {
                const int sl = (t + 1) & (DEPTH - 1);
#pragma unroll
                for (int j = 0; j < JPER; j++) r[j] = ring[sl][off[j]];
            }

            // 3) alpha recurrence for step t (critical path: shfl + 3 flops)
            if (t < Tb) {
                float h3 = __shfl_up_sync(FULL, a3r, 1);
                float h4 = __shfl_up_sync(FULL, a4r, 1);
                if (lane == 0) { h3 = 0.f; h4 = 0.f; }

                const float n0 = (a0  + h4  + skipf[0] * h3 ) * ee[cur][0];
                const float n1 = (a1r + a0  + skipf[1] * h4 ) * ee[cur][1];
                const float n2 = (a2r + a1r + skipf[2] * a0 ) * ee[cur][2];
                const float n3 = (a3r + a2r + skipf[3] * a1r) * ee[cur][3];
                const float n4 = (a4r + a3r + skipf[4] * a2r) * ee[cur][4];
                a0 = n0; a1r = n1; a2r = n2; a3r = n3; a4r = n4;
            }

            // 4) every 4th step: exact power-of-two rescale, folded into the
            //    NEXT step's emissions (off the shfl chain). Only if a next
            //    step exists (esum must match an actually-applied factor).
            float fscale = 1.0f;
            if (k == 3 && (t + 1) < Tb) {
                float m = fmaxf(fmaxf(fmaxf(a0, a1r), fmaxf(a2r, a3r)), a4r);
                unsigned mu = __reduce_max_sync(FULL, __float_as_uint(m));
                if (mu != 0u) {
                    const int ef = (int)(mu >> 23);
                    int kk = EF_TARGET - ef;
                    kk = kk > 127 ? 127 : (kk < -126 ? -126 : kk);
                    fscale = __int_as_float((unsigned)(127 + kk) << 23);  // 2^kk exact
                    esum -= kk;
                }
            }

            // 5) build emissions for step t+1
#pragma unroll
            for (int j = 0; j < JPER; j++)
                ee[nxt][j] = (r[j] + EPSF) * (vsf[j] * fscale);
        }
    }

    // loss = -( log(alpha[2Ll] + alpha[2Ll-1]) + esum*ln2 )
    const int se0 = 2 * Ll;
    const int se1 = 2 * Ll - 1;
    const int l0 = se0 / JPER, j0 = se0 % JPER;
    const int l1 = se1 / JPER, j1 = se1 % JPER;

    const float v0 = pick5(a0, a1r, a2r, a3r, a4r, j0);
    const float v1 = pick5(a0, a1r, a2r, a3r, a4r, j1);
    const float fa1 = __shfl_sync(FULL, v0, l0);
    const float fa2 = __shfl_sync(FULL, v1, l1);

    if (lane == 0) {
        const float s = fmaxf(fa1 + fa2, 1e-43f);
        const float loss = -(logf(s) + (float)esum * 0.6931471805599453f);
        out[b] = loss;
    }

    cpwait<0>();   // drain stragglers before exit
}

extern "C" void kernel_launch(void* const* d_in, const int* in_sizes, int n_in,
                              void* d_out, int out_size)
{
    const int*   y_true       = (const int*)  d_in[0];   // [B,L] int32
    const float* y_pred       = (const float*)d_in[1];   // [B,T,C] f32
    const int*   input_length = (const int*)  d_in[2];   // [B,1] int32
    const int*   label_length = (const int*)  d_in[3];   // [B,1] int32
    float*       out          = (float*)d_out;           // [B,1] f32

    ctc_fused_kernel<<<BQ, 32>>>(y_true, y_pred, input_length, label_length, out);
}

// round 17
// speedup vs baseline: 2.1294x; 2.1294x over previous
#include <cuda_runtime.h>
#include <cstdint>

// Problem constants (fixed by the dataset)
#define BQ    128
#define TT    512
#define CC    1024
#define LL    64
#define SS    129           // 2*LL + 1 extended states
#define BLANKC 1023
#define EPSF  1e-7f
#define JPER  5             // states per lane (26 lanes * 5 = 130 >= 129)
#define DEPTH 16            // cp.async pipeline depth (steps in flight)
#define RSTRIDE 68          // smem ring row stride (66 used, padded)
#define EF_TARGET 226       // rescale target: warp max in [2^99, 2^100)

__device__ __forceinline__ void cpasync4(uint32_t saddr, const float* g) {
    asm volatile("cp.async.ca.shared.global [%0], [%1], 4;" :: "r"(saddr), "l"(g));
}
__device__ __forceinline__ void cpcommit() {
    asm volatile("cp.async.commit_group;");
}
template <int N> __device__ __forceinline__ void cpwait() {
    asm volatile("cp.async.wait_group %0;" :: "n"(N));
}

__device__ __forceinline__ float pick5(const float a0, const float a1, const float a2,
                                       const float a3, const float a4, int j) {
    float r = a0;
    if (j == 1) r = a1;
    else if (j == 2) r = a2;
    else if (j == 3) r = a3;
    else if (j == 4) r = a4;
    return r;
}

__global__ __launch_bounds__(32, 1)
void ctc_fused_kernel(const int* __restrict__ y_true,
                      const float* __restrict__ y_pred,
                      const int* __restrict__ input_length,
                      const int* __restrict__ label_length,
                      float* __restrict__ out)
{
    __shared__ float ring[DEPTH][RSTRIDE];   // per-step compact emissions (66 used)

    const int b    = blockIdx.x;
    const int lane = threadIdx.x;
    const unsigned FULL = 0xffffffffu;

    const int Tb = input_length[b];          // warp-uniform
    const int Ll = label_length[b];
    const int Sb = 2 * Ll + 1;

    const int*   lrow = y_true + b * LL;
    const float* prow = y_pred + (size_t)b * TT * CC;

    // Each lane gathers label classes lane and lane+32; lane 0 also the blank.
    const int lab0 = lrow[lane];
    const int lab1 = lrow[lane + 32];

    const uint32_t smem_base = (uint32_t)__cvta_generic_to_shared(&ring[0][0]);

    // Per-lane static state metadata: states s = lane*5 + j
    int   off[JPER];     // index into compact emission row (s>>1 label, 64 blank)
    float vsf[JPER];     // validity mask (0 for invalid states)
    float skipf[JPER];
#pragma unroll
    for (int j = 0; j < JPER; j++) {
        const int s = lane * JPER + j;
        const bool v = (s < SS) && (s < Sb);
        int  o  = 64;                       // blank slot (also sink for invalid)
        bool sk = false;
        if (v && (s & 1)) {
            o = s >> 1;
            if (s >= 3) sk = (lrow[o] != lrow[o - 1]);
        }
        off[j]   = o;
        vsf[j]   = v ? 1.0f : 0.0f;
        skipf[j] = sk ? 1.0f : 0.0f;
    }

    // alpha init: linear domain, mass 1 at s=0
    float a0 = 0.f, a1r = 0.f, a2r = 0.f, a3r = 0.f, a4r = 0.f;
    if (lane == 0) a0 = 1.0f;

    // ---- prologue: fill the cp.async pipeline with steps 0..DEPTH-1 ----
#pragma unroll
    for (int t = 0; t < DEPTH; t++) {
        const float* pr = prow + (size_t)t * CC;
        const uint32_t wa = smem_base + (uint32_t)((t & (DEPTH - 1)) * RSTRIDE + lane) * 4u;
        cpasync4(wa, pr + lab0);
        cpasync4(wa + 32u * 4u, pr + lab1);
        if (lane == 0)
            cpasync4(smem_base + (uint32_t)((t & (DEPTH - 1)) * RSTRIDE + 64) * 4u, pr + BLANKC);
        cpcommit();
    }

    // ee[parity][j]: emission values for the current / next step, EPS and
    // validity (and any pending rescale factor) pre-folded.
    float ee[2][JPER];
    cpwait<DEPTH - 1>();                     // step 0 group complete
#pragma unroll
    for (int j = 0; j < JPER; j++)
        ee[0][j] = (ring[0][off[j]] + EPSF) * vsf[j];

    int esum = 0;   // exact power-of-two rescale accumulator
                    // invariant: alpha_true = alpha_stored * 2^esum

    for (int tb = 0; tb < Tb; tb += 4) {
#pragma unroll
        for (int k = 0; k < 4; k++) {
            const int t   = tb + k;
            const int cur = t & 1;
            const int nxt = cur ^ 1;

            // 1) issue prefetch for step t+DEPTH (clamped row; harmless extras)
            {
                const int tp  = t + DEPTH;
                const int row = tp < TT ? tp : TT - 1;
                const float* pr = prow + (size_t)row * CC;
                const uint32_t wa = smem_base + (uint32_t)((tp & (DEPTH - 1)) * RSTRIDE + lane) * 4u;
                cpasync4(wa, pr + lab0);
                cpasync4(wa + 32u * 4u, pr + lab1);
                if (lane == 0)
                    cpasync4(smem_base + (uint32_t)((tp & (DEPTH - 1)) * RSTRIDE + 64) * 4u, pr + BLANKC);
                cpcommit();
            }
            // 2) ensure step t+1's group is complete, read its raw values
            cpwait<DEPTH - 1>();
            float r[JPER];
            {
                const int sl = (t + 1) & (DEPTH - 1);
#pragma unroll
                for (int j = 0; j < JPER; j++) r[j] = ring[sl][off[j]];
            }

            // 3) alpha recurrence for step t (critical path: shfl + 3 flops)
            if (t < Tb) {
                float h3 = __shfl_up_sync(FULL, a3r, 1);
                float h4 = __shfl_up_sync(FULL, a4r, 1);
                if (lane == 0) { h3 = 0.f; h4 = 0.f; }

                const float n0 = (a0  + h4  + skipf[0] * h3 ) * ee[cur][0];
                const float n1 = (a1r + a0  + skipf[1] * h4 ) * ee[cur][1];
                const float n2 = (a2r + a1r + skipf[2] * a0 ) * ee[cur][2];
                const float n3 = (a3r + a2r + skipf[3] * a1r) * ee[cur][3];
                const float n4 = (a4r + a3r + skipf[4] * a2r) * ee[cur][4];
                a0 = n0; a1r = n1; a2r = n2; a3r = n3; a4r = n4;
            }

            // 4) every 4th step: exact power-of-two rescale, folded into the
            //    NEXT step's emissions (off the shfl chain). Only if a next
            //    step exists (esum must match an actually-applied factor).
            float fscale = 1.0f;
            if (k == 3 && (t + 1) < Tb) {
                float m = fmaxf(fmaxf(fmaxf(a0, a1r), fmaxf(a2r, a3r)), a4r);
                unsigned mu = __reduce_max_sync(FULL, __float_as_uint(m));
                if (mu != 0u) {
                    const int ef = (int)(mu >> 23);
                    int kk = EF_TARGET - ef;
                    kk = kk > 127 ? 127 : (kk < -126 ? -126 : kk);
                    fscale = __int_as_float((unsigned)(127 + kk) << 23);  // 2^kk exact
                    esum -= kk;
                }
            }

            // 5) build emissions for step t+1
#pragma unroll
            for (int j = 0; j < JPER; j++)
                ee[nxt][j] = (r[j] + EPSF) * (vsf[j] * fscale);
        }
    }

    // loss = -( log(alpha[2Ll] + alpha[2Ll-1]) + esum*ln2 )
    const int se0 = 2 * Ll;
    const int se1 = 2 * Ll - 1;
    const int l0 = se0 / JPER, j0 = se0 % JPER;
    const int l1 = se1 / JPER, j1 = se1 % JPER;

    const float v0 = pick5(a0, a1r, a2r, a3r, a4r, j0);
    const float v1 = pick5(a0, a1r, a2r, a3r, a4r, j1);
    const float fa1 = __shfl_sync(FULL, v0, l0);
    const float fa2 = __shfl_sync(FULL, v1, l1);

    if (lane == 0) {
        const float s = fmaxf(fa1 + fa2, 1e-43f);
        const float loss = -(logf(s) + (float)esum * 0.6931471805599453f);
        out[b] = loss;
    }
}

extern "C" void kernel_launch(void* const* d_in, const int* in_sizes, int n_in,
                              void* d_out, int out_size)
{
    const int*   y_true       = (const int*)  d_in[0];   // [B,L] int32
    const float* y_pred       = (const float*)d_in[1];   // [B,T,C] f32
    const int*   input_length = (const int*)  d_in[2];   // [B,1] int32
    const int*   label_length = (const int*)  d_in[3];   // [B,1] int32
    float*       out          = (float*)d_out;           // [B,1] f32

    ctc_fused_kernel<<<BQ, 32>>>(y_true, y_pred, input_length, label_length, out);
}